// round 2
// baseline (speedup 1.0000x reference)
#include <cuda_runtime.h>

#define TN 32768
#define TLOOP 32799
#define NCHUNK 2050
#define NSTEPS (NCHUNK*16)   /* 32800 */
#define NBC 14
#define NACL 10
#define NACG 35
#define KACN 52
#define K0 20
#define K1 32
#define PADL 50              /* (K0-1)+(K1-1) */
#define XPLEN (TN + PADL)    /* 32818 */
#define RELSTRIDE 32832

__device__ float g_xp[XPLEN];
__device__ float g_drive[NSTEPS*NBC];
__device__ float g_rel[2*NBC*RELSTRIDE];
__device__ float g_kbc[NBC*K0];
__device__ float g_kglu[K1];

__device__ __forceinline__ float ftanh(float x){
    float y; asm("tanh.approx.f32 %0, %1;" : "=f"(y) : "f"(x)); return y;
}
__device__ __forceinline__ float fex2(float x){
    float y; asm("ex2.approx.f32 %0, %1;" : "=f"(y) : "f"(x)); return y;
}
__device__ __forceinline__ float frcp(float x){
    float y; asm("rcp.approx.f32 %0, %1;" : "=f"(y) : "f"(x)); return y;
}

// double-exponential AC kernel -> IIR coefficients (exact FIR-equivalent with
// truncation correction): kern(L) = A*r1^L - B*r2^L (L=0 newest), L2-normalized
__device__ __forceinline__ void ac_coef(float ltr, float ltd,
    float &A, float &B, float &r1, float &r2, float &c1, float &c2){
    float tr = expf(ltr), td = expf(ltd);
    float beta = (td + tr) / (td * tr);
    float n2 = 0.f;
    for (int k = 0; k < KACN; k++){
        float t = 0.8f - (float)k * (1.0f/64.0f);
        float v = expf(-t/td) - expf(-beta*t);
        n2 = fmaf(v, v, n2);
    }
    float inv = 1.0f / sqrtf(n2);
    const float c0 = 0.8f - 51.0f*(1.0f/64.0f);
    A  = expf(-c0/td) * inv;
    B  = expf(-beta*c0) * inv;
    r1 = expf(-1.0f/(64.0f*td));
    r2 = expf(-beta*(1.0f/64.0f));
    c1 = expf(-0.8125f/td);        /* r1^52 */
    c2 = expf(-beta*0.8125f);      /* r2^52 */
}

// ---------------- setup: BC biphasic kernels + iGluSnFR kernel ----------------
__global__ void setup_kernel(const float* __restrict__ lks){
    int t = threadIdx.x;
    if (t < NBC){
        float speed = expf(lks[t]);
        float ct = (t < 5) ? -1.0f : 1.0f;
        float vals[K0]; float n2 = 0.f;
        #pragma unroll
        for (int j = 0; j < K0; j++){
            float ts = (float)j * (1.0f/64.0f) * speed;
            float a = ts / 0.05f, b = ts / 0.1f;
            float v = a*a*expf(-a) - 0.8f*b*b*expf(-b);
            v *= ct;
            vals[j] = v; n2 += v*v;
        }
        float inv = 1.0f / sqrtf(n2);
        #pragma unroll
        for (int j = 0; j < K0; j++) g_kbc[t*K0+j] = vals[j]*inv;
    }
    if (t == 32){
        float vals[K1]; float s = 0.f;
        #pragma unroll
        for (int j = 0; j < K1; j++){
            float tg = (float)j * (1.0f/64.0f);
            float v = (1.0f - expf(-tg/0.02f)) * expf(-tg/0.1f);
            vals[j] = v; s += v;
        }
        #pragma unroll
        for (int j = 0; j < K1; j++) g_kglu[j] = vals[j]/s;
    }
}

// ---------------- stimulus affine + edge padding ----------------
__global__ void xp_kernel(const float* __restrict__ x,
                          const float* __restrict__ sb,
                          const float* __restrict__ ss){
    int i = blockIdx.x*blockDim.x + threadIdx.x;
    if (i >= XPLEN) return;
    float es = expf(ss[0]); float b = sb[0];
    int s = i - PADL; if (s < 0) s = 0;
    g_xp[i] = x[s]*es + b;
}

// ---------------- per-BC 20-tap FIR -> drive[NSTEPS][NBC] ----------------
__global__ void drive_kernel(){
    __shared__ float skb[NBC*K0];
    int tid = threadIdx.x;
    for (int i = tid; i < NBC*K0; i += blockDim.x) skb[i] = g_kbc[i];
    __syncthreads();
    int n = blockIdx.x*blockDim.x + tid;
    if (n >= NSTEPS) return;
    if (n >= TLOOP){
        #pragma unroll
        for (int c = 0; c < NBC; c++) g_drive[n*NBC+c] = 0.f;
        return;
    }
    float xw[K0];
    #pragma unroll
    for (int j = 0; j < K0; j++) xw[j] = g_xp[n + j];
    #pragma unroll
    for (int c = 0; c < NBC; c++){
        float a0 = 0.f, a1 = 0.f;
        #pragma unroll
        for (int j = 0; j < K0; j++){
            float w = skb[c*K0+j];
            float v = xw[K0-1-j];
            if (j & 1) a1 = fmaf(w, v, a1); else a0 = fmaf(w, v, a0);
        }
        g_drive[n*NBC+c] = a0 + a1;
    }
}

// ---------------- the sequential scan: 2 blocks (pathways) x 1 warp ----------------
__global__ void __launch_bounds__(32,1) scan_kernel(
    const float* __restrict__ P_sigoff, const float* __restrict__ P_lslope,
    const float* __restrict__ P_lp01,  const float* __restrict__ P_lp12,
    const float* __restrict__ P_lipc,  const float* __restrict__ P_lrrpc,
    const float* __restrict__ P_ipst,  const float* __restrict__ P_rrpst,
    const float* __restrict__ P_laclbc, const float* __restrict__ P_lbcacl,
    const float* __restrict__ P_acltr, const float* __restrict__ P_acltd,
    const float* __restrict__ P_aclsl, const float* __restrict__ P_aclof,
    const float* __restrict__ P_lacgbc, const float* __restrict__ P_lbcacg,
    const float* __restrict__ P_acgtr, const float* __restrict__ P_acgtd,
    const float* __restrict__ P_acgsl, const float* __restrict__ P_acgof,
    const float* __restrict__ P_laclacg, const float* __restrict__ P_bcnoff)
{
    const int path = blockIdx.x;
    const int l = threadIdx.x;
    __shared__ float ringA[NACL*53];
    __shared__ float ringG[NACG*53];
    __shared__ float dbuf[2][16*NBC];
    for (int i = l; i < NACL*53; i += 32) ringA[i] = 0.f;
    for (int i = l; i < NACG*53; i += 32) ringG[i] = 0.f;

    // ---- BC role (lane < 14): exp-form final sigmoid, log2e+slope pre-folded ----
    float cP=0.f, mBC=0.f, c_p01=0.f, c_p12=0.f, c_ipcap=0.f, c_irrp=0.f;
    float ip=0.f, rrp=0.f;
    float wfbAE[NACL], wfbGE[NACG];
    #pragma unroll
    for (int j = 0; j < NACL; j++) wfbAE[j] = 0.f;
    #pragma unroll
    for (int j = 0; j < NACG; j++) wfbGE[j] = 0.f;
    if (l < NBC){
        float off   = P_sigoff[l] + (path ? P_bcnoff[l] : 0.f);
        float slope = expf(P_lslope[l]);
        mBC = -slope * 1.44269504f;          /* exp(-z) = 2^(mBC * total) */
        c_p01   = expf(P_lp01[l]);
        c_p12   = expf(P_lp12[l]);
        c_ipcap = expf(P_lipc[l]);
        float rc = expf(P_lrrpc[l]);
        c_irrp = 1.0f / rc;
        ip  = c_ipcap / (1.0f + expf(-P_ipst[l]));
        rrp = rc      / (1.0f + expf(-P_rrpst[l]));
        float sA = 0.f, sG = 0.f;
        #pragma unroll
        for (int j = 0; j < NACL; j++){
            float w = -expf(P_laclbc[l*NACL+j]);
            sA += w; wfbAE[j] = 0.5f*mBC*w;
        }
        if (path){
            #pragma unroll
            for (int j = 0; j < NACG; j++){
                float w = -expf(P_lacgbc[l*NACG+j]);
                sG += w; wfbGE[j] = 0.5f*mBC*w;
            }
        }
        cP = mBC*(0.5f*(sA+sG) - off);
    }

    // ---- ACL role (lane < 10): tanh-form, half-slope pre-folded into state ----
    float kA1=0.f,kA2=0.f,aR1=1.f,aR2=1.f,kA1c=0.f,kA2c=0.f,caA=0.f;
    float wyA[NBC];
    #pragma unroll
    for (int j = 0; j < NBC; j++) wyA[j] = 0.f;
    if (l < NACL){
        float A,B,r1,r2,c1,c2;
        ac_coef(P_acltr[l], P_acltd[l], A,B,r1,r2,c1,c2);
        float ha = 0.5f*expf(P_aclsl[l]);
        kA1 = ha*A; kA2 = ha*B; aR1=r1; aR2=r2;
        kA1c = kA1*c1; kA2c = kA2*c2;
        caA = -ha*P_aclof[l];
        #pragma unroll
        for (int j = 0; j < NBC; j++) wyA[j] = expf(P_lbcacl[l*NBC+j]);
    }

    // ---- ACG roles (pathway 2 only): g = lane (0..31), h = lane+32 (lanes 0..2) ----
    float kG1=0.f,kG2=0.f,gR1=1.f,gR2=1.f,kG1c=0.f,kG2c=0.f,cgG=0.f;
    float kH1=0.f,kH2=0.f,hR1=1.f,hR2=1.f,kH1c=0.f,kH2c=0.f,cgH=0.f;
    float wGaE[NACL], wHaE[NACL], wyG[NBC], wyH[NBC];
    #pragma unroll
    for (int j = 0; j < NACL; j++){ wGaE[j]=0.f; wHaE[j]=0.f; }
    #pragma unroll
    for (int j = 0; j < NBC; j++){ wyG[j]=0.f; wyH[j]=0.f; }
    if (path){
        float A,B,r1,r2,c1,c2;
        ac_coef(P_acgtr[l], P_acgtd[l], A,B,r1,r2,c1,c2);
        float hg = 0.5f*expf(P_acgsl[l]);
        kG1 = hg*A; kG2 = hg*B; gR1=r1; gR2=r2;
        kG1c = kG1*c1; kG2c = kG2*c2;
        float sw = 0.f;
        #pragma unroll
        for (int j = 0; j < NACL; j++){
            float w = -expf(P_laclacg[l*NACL+j]);
            sw += w; wGaE[j] = hg*0.5f*w;
        }
        cgG = hg*(0.5f*sw - P_acgof[l]);
        #pragma unroll
        for (int j = 0; j < NBC; j++) wyG[j] = expf(P_lbcacg[l*NBC+j]);
        if (l < 3){
            int h = l + 32;
            ac_coef(P_acgtr[h], P_acgtd[h], A,B,r1,r2,c1,c2);
            float hh = 0.5f*expf(P_acgsl[h]);
            kH1 = hh*A; kH2 = hh*B; hR1=r1; hR2=r2;
            kH1c = kH1*c1; kH2c = kH2*c2;
            float swh = 0.f;
            #pragma unroll
            for (int j = 0; j < NACL; j++){
                float w = -expf(P_laclacg[h*NACL+j]);
                swh += w; wHaE[j] = hh*0.5f*w;
            }
            cgH = hh*(0.5f*swh - P_acgof[h]);
            #pragma unroll
            for (int j = 0; j < NBC; j++) wyH[j] = expf(P_lbcacg[h*NBC+j]);
        }
    }
    __syncwarp();

    float* relrow = g_rel + (path*NBC + ((l < NBC) ? l : 0))*RELSTRIDE;
    float A1=0.f,A2=0.f,G1=0.f,G2=0.f,H1=0.f,H2=0.f;
    int ri = 0;

    float fd0,fd1,fd2,fd3,fd4,fd5,fd6;
#define LOADCHUNK(k) do{ const float* _p = g_drive + (k)*224 + l; \
        fd0=_p[0]; fd1=_p[32]; fd2=_p[64]; fd3=_p[96]; fd4=_p[128]; fd5=_p[160]; fd6=_p[192]; }while(0)
#define STORECHUNK(bi) do{ float* _q = dbuf[bi] + l; \
        _q[0]=fd0; _q[32]=fd1; _q[64]=fd2; _q[96]=fd3; _q[128]=fd4; _q[160]=fd5; _q[192]=fd6; }while(0)

    LOADCHUNK(0); STORECHUNK(0); LOADCHUNK(1);
    __syncwarp();

    if (path == 0){
        // ---------- LNR pathway: ACL feedback only ----------
        for (int c = 0; c < NCHUNK; c++){
            int cur = c & 1;
            STORECHUNK(cur^1);
            int nk = (c+2 < NCHUNK) ? (c+2) : (NCHUNK-1);
            LOADCHUNK(nk);
            __syncwarp();
            const float* db = dbuf[cur];
            int tbase = c*16;
            #pragma unroll 4
            for (int i = 0; i < 16; i++){
                /* ---- off-chain top work ---- */
                float yoA = (l < NACL) ? ringA[l*53+ri] : 0.f;
                float xi  = (l < NBC) ? db[i*NBC + l] : 0.f;
                float rrp_h = 0.5f*rrp;
                float t12 = c_p12*ip*(1.0f - rrp*c_irrp);
                float ip_n = ip + c_p01*(c_ipcap - ip) - t12;
                float rrp_m = rrp + t12;
                float bA1 = fmaf(-kA1c, yoA, aR1*A1);
                float bA2 = fmaf(-kA2c, yoA, aR2*A2);
                /* ---- critical chain ---- */
                float tvA = ftanh((A1 - A2) + caA);
                float fb0 = fmaf(mBC, xi, cP), fb1 = 0.f;
                #pragma unroll
                for (int j = 0; j < NACL; j++){
                    float v = __shfl_sync(0xffffffffu, tvA, j);
                    if (j & 1) fb1 = fmaf(wfbAE[j], v, fb1);
                    else       fb0 = fmaf(wfbAE[j], v, fb0);
                }
                float e = fex2(fb0 + fb1);
                float relv = rrp * frcp(1.0f + e);
                ip = ip_n; rrp = rrp_m - relv;
                if (l < NBC) relrow[tbase+i] = relv;
                float y0 = 0.f, y1 = 0.f;
                #pragma unroll
                for (int j = 0; j < NBC; j++){
                    float v = __shfl_sync(0xffffffffu, relv, j);
                    if (j & 1) y1 = fmaf(wyA[j], v, y1);
                    else       y0 = fmaf(wyA[j], v, y0);
                }
                float yA = y0 + y1;
                if (l < NACL) ringA[l*53+ri] = yA;
                A1 = fmaf(kA1, yA, bA1);
                A2 = fmaf(kA2, yA, bA2);
                ri = (ri == KACN-1) ? 0 : ri+1;
            }
            __syncwarp();
        }
    } else {
        // ---------- BCN pathway: ACL + ACG feedback ----------
        for (int c = 0; c < NCHUNK; c++){
            int cur = c & 1;
            STORECHUNK(cur^1);
            int nk = (c+2 < NCHUNK) ? (c+2) : (NCHUNK-1);
            LOADCHUNK(nk);
            __syncwarp();
            const float* db = dbuf[cur];
            int tbase = c*16;
            #pragma unroll 2
            for (int i = 0; i < 16; i++){
                /* ---- off-chain top work ---- */
                float yoA = (l < NACL) ? ringA[l*53+ri] : 0.f;
                float yoG = ringG[l*53+ri];
                float yoH = (l < 3) ? ringG[(l+32)*53+ri] : 0.f;
                float xi  = (l < NBC) ? db[i*NBC + l] : 0.f;
                float rrp_h = 0.5f*rrp; (void)rrp_h;
                float t12 = c_p12*ip*(1.0f - rrp*c_irrp);
                float ip_n = ip + c_p01*(c_ipcap - ip) - t12;
                float rrp_m = rrp + t12;
                float bA1 = fmaf(-kA1c, yoA, aR1*A1);
                float bA2 = fmaf(-kA2c, yoA, aR2*A2);
                float bG1 = fmaf(-kG1c, yoG, gR1*G1);
                float bG2 = fmaf(-kG2c, yoG, gR2*G2);
                float bH1 = fmaf(-kH1c, yoH, hR1*H1);
                float bH2 = fmaf(-kH2c, yoH, hR2*H2);
                float baseG = (G1 - G2) + cgG;
                float baseH = (H1 - H2) + cgH;
                /* ---- critical chain ---- */
                float tvA = ftanh((A1 - A2) + caA);
                float pg0 = baseG, pg1 = 0.f, ph0 = baseH, ph1 = 0.f;
                float fb0 = fmaf(mBC, xi, cP), fb1 = 0.f, fb2 = 0.f, fb3 = 0.f;
                #pragma unroll
                for (int j = 0; j < NACL; j++){
                    float v = __shfl_sync(0xffffffffu, tvA, j);
                    if (j & 1){ pg1 = fmaf(wGaE[j], v, pg1); ph1 = fmaf(wHaE[j], v, ph1); }
                    else      { pg0 = fmaf(wGaE[j], v, pg0); ph0 = fmaf(wHaE[j], v, ph0); }
                    if (j & 1) fb1 = fmaf(wfbAE[j], v, fb1);
                    else       fb0 = fmaf(wfbAE[j], v, fb0);
                }
                float tvG = ftanh(pg0 + pg1);
                float tvH = ftanh(ph0 + ph1);
                #pragma unroll
                for (int j = 0; j < 32; j++){
                    float v = __shfl_sync(0xffffffffu, tvG, j);
                    fb0 = (j & 3) == 0 ? fmaf(wfbGE[j], v, fb0) : fb0;
                    fb1 = (j & 3) == 1 ? fmaf(wfbGE[j], v, fb1) : fb1;
                    fb2 = (j & 3) == 2 ? fmaf(wfbGE[j], v, fb2) : fb2;
                    fb3 = (j & 3) == 3 ? fmaf(wfbGE[j], v, fb3) : fb3;
                }
                #pragma unroll
                for (int j = 0; j < 3; j++){
                    float v = __shfl_sync(0xffffffffu, tvH, j);
                    if (j == 0) fb0 = fmaf(wfbGE[32], v, fb0);
                    if (j == 1) fb1 = fmaf(wfbGE[33], v, fb1);
                    if (j == 2) fb2 = fmaf(wfbGE[34], v, fb2);
                }
                float e = fex2((fb0 + fb1) + (fb2 + fb3));
                float relv = rrp * frcp(1.0f + e);
                ip = ip_n; rrp = rrp_m - relv;
                if (l < NBC) relrow[tbase+i] = relv;
                float ya0=0.f,ya1=0.f,yg0=0.f,yg1=0.f,yh0=0.f,yh1=0.f;
                #pragma unroll
                for (int j = 0; j < NBC; j++){
                    float v = __shfl_sync(0xffffffffu, relv, j);
                    if (j & 1){
                        ya1 = fmaf(wyA[j], v, ya1);
                        yg1 = fmaf(wyG[j], v, yg1);
                        yh1 = fmaf(wyH[j], v, yh1);
                    } else {
                        ya0 = fmaf(wyA[j], v, ya0);
                        yg0 = fmaf(wyG[j], v, yg0);
                        yh0 = fmaf(wyH[j], v, yh0);
                    }
                }
                float yA = ya0+ya1, yG = yg0+yg1, yH = yh0+yh1;
                if (l < NACL) ringA[l*53+ri] = yA;
                ringG[l*53+ri] = yG;
                if (l < 3) ringG[(l+32)*53+ri] = yH;
                A1 = fmaf(kA1, yA, bA1);
                A2 = fmaf(kA2, yA, bA2);
                G1 = fmaf(kG1, yG, bG1);
                G2 = fmaf(kG2, yG, bG2);
                H1 = fmaf(kH1, yH, bH1);
                H2 = fmaf(kH2, yH, bH2);
                ri = (ri == KACN-1) ? 0 : ri+1;
            }
            __syncwarp();
        }
    }
#undef LOADCHUNK
#undef STORECHUNK
}

// ---------------- iGluSnFR readout: 32-tap FIR over rel ----------------
__global__ void out_kernel(float* __restrict__ out){
    __shared__ float skg[K1];
    int tid = threadIdx.x;
    if (tid < K1) skg[tid] = g_kglu[tid];
    __syncthreads();
    int oid = blockIdx.x*blockDim.x + tid;
    if (oid >= 2*NBC*TN) return;
    int n  = oid & (TN-1);
    int pc = oid >> 15;
    const float* r = g_rel + pc*RELSTRIDE + n;
    float a0 = 0.f, a1 = 0.f;
    #pragma unroll
    for (int j = 0; j < K1; j++){
        float v = r[K1-1-j];
        if (j & 1) a1 = fmaf(skg[j], v, a1);
        else       a0 = fmaf(skg[j], v, a0);
    }
    out[oid] = a0 + a1;
}

extern "C" void kernel_launch(void* const* d_in, const int* in_sizes, int n_in,
                              void* d_out, int out_size){
    (void)in_sizes; (void)n_in; (void)out_size;
    const float* x  = (const float*)d_in[0];
    const float* sb = (const float*)d_in[1];
    const float* ss = (const float*)d_in[2];

    setup_kernel<<<1, 64>>>((const float*)d_in[3]);
    xp_kernel<<<(XPLEN+255)/256, 256>>>(x, sb, ss);
    drive_kernel<<<(NSTEPS+127)/128, 128>>>();
    scan_kernel<<<2, 32>>>(
        (const float*)d_in[4],  (const float*)d_in[5],
        (const float*)d_in[6],  (const float*)d_in[7],
        (const float*)d_in[8],  (const float*)d_in[9],
        (const float*)d_in[10], (const float*)d_in[11],
        (const float*)d_in[12], (const float*)d_in[13],
        (const float*)d_in[14], (const float*)d_in[15],
        (const float*)d_in[16], (const float*)d_in[17],
        (const float*)d_in[18], (const float*)d_in[19],
        (const float*)d_in[20], (const float*)d_in[21],
        (const float*)d_in[22], (const float*)d_in[23],
        (const float*)d_in[24], (const float*)d_in[25]);
    out_kernel<<<(2*NBC*TN+255)/256, 256>>>((float*)d_out);
}

// round 3
// speedup vs baseline: 1.1082x; 1.1082x over previous
#include <cuda_runtime.h>

#define TN 32768
#define TLOOP 32799
#define NCHUNK 2050
#define NSTEPS (NCHUNK*16)   /* 32800 */
#define NBC 14
#define NACL 10
#define NACG 35
#define KACN 52
#define K0 20
#define K1 32
#define PADL 50              /* (K0-1)+(K1-1) */
#define XPLEN (TN + PADL)    /* 32818 */
#define RELSTRIDE 32832

__device__ float g_xp[XPLEN];
__device__ float g_drive[NSTEPS*NBC];
__device__ float g_rel[2*NBC*RELSTRIDE];
__device__ float g_kbc[NBC*K0];
__device__ float g_kglu[K1];

__device__ __forceinline__ float ftanh(float x){
    float y; asm("tanh.approx.f32 %0, %1;" : "=f"(y) : "f"(x)); return y;
}
__device__ __forceinline__ float fex2(float x){
    float y; asm("ex2.approx.f32 %0, %1;" : "=f"(y) : "f"(x)); return y;
}
__device__ __forceinline__ float frcp(float x){
    float y; asm("rcp.approx.f32 %0, %1;" : "=f"(y) : "f"(x)); return y;
}

// double-exponential AC kernel -> IIR coefficients (exact FIR-equivalent with
// truncation correction): kern(L) = A*r1^L - B*r2^L (L=0 newest), L2-normalized
__device__ __forceinline__ void ac_coef(float ltr, float ltd,
    float &A, float &B, float &r1, float &r2, float &c1, float &c2){
    float tr = expf(ltr), td = expf(ltd);
    float beta = (td + tr) / (td * tr);
    float n2 = 0.f;
    for (int k = 0; k < KACN; k++){
        float t = 0.8f - (float)k * (1.0f/64.0f);
        float v = expf(-t/td) - expf(-beta*t);
        n2 = fmaf(v, v, n2);
    }
    float inv = 1.0f / sqrtf(n2);
    const float c0 = 0.8f - 51.0f*(1.0f/64.0f);
    A  = expf(-c0/td) * inv;
    B  = expf(-beta*c0) * inv;
    r1 = expf(-1.0f/(64.0f*td));
    r2 = expf(-beta*(1.0f/64.0f));
    c1 = expf(-0.8125f/td);        /* r1^52 */
    c2 = expf(-beta*0.8125f);      /* r2^52 */
}

// ---------------- setup: BC biphasic kernels + iGluSnFR kernel ----------------
__global__ void setup_kernel(const float* __restrict__ lks){
    int t = threadIdx.x;
    if (t < NBC){
        float speed = expf(lks[t]);
        float ct = (t < 5) ? -1.0f : 1.0f;
        float vals[K0]; float n2 = 0.f;
        #pragma unroll
        for (int j = 0; j < K0; j++){
            float ts = (float)j * (1.0f/64.0f) * speed;
            float a = ts / 0.05f, b = ts / 0.1f;
            float v = a*a*expf(-a) - 0.8f*b*b*expf(-b);
            v *= ct;
            vals[j] = v; n2 += v*v;
        }
        float inv = 1.0f / sqrtf(n2);
        #pragma unroll
        for (int j = 0; j < K0; j++) g_kbc[t*K0+j] = vals[j]*inv;
    }
    if (t == 32){
        float vals[K1]; float s = 0.f;
        #pragma unroll
        for (int j = 0; j < K1; j++){
            float tg = (float)j * (1.0f/64.0f);
            float v = (1.0f - expf(-tg/0.02f)) * expf(-tg/0.1f);
            vals[j] = v; s += v;
        }
        #pragma unroll
        for (int j = 0; j < K1; j++) g_kglu[j] = vals[j]/s;
    }
}

// ---------------- stimulus affine + edge padding ----------------
__global__ void xp_kernel(const float* __restrict__ x,
                          const float* __restrict__ sb,
                          const float* __restrict__ ss){
    int i = blockIdx.x*blockDim.x + threadIdx.x;
    if (i >= XPLEN) return;
    float es = expf(ss[0]); float b = sb[0];
    int s = i - PADL; if (s < 0) s = 0;
    g_xp[i] = x[s]*es + b;
}

// ---------------- per-BC 20-tap FIR -> drive[NSTEPS][NBC] ----------------
__global__ void drive_kernel(){
    __shared__ float skb[NBC*K0];
    int tid = threadIdx.x;
    for (int i = tid; i < NBC*K0; i += blockDim.x) skb[i] = g_kbc[i];
    __syncthreads();
    int n = blockIdx.x*blockDim.x + tid;
    if (n >= NSTEPS) return;
    if (n >= TLOOP){
        #pragma unroll
        for (int c = 0; c < NBC; c++) g_drive[n*NBC+c] = 0.f;
        return;
    }
    float xw[K0];
    #pragma unroll
    for (int j = 0; j < K0; j++) xw[j] = g_xp[n + j];
    #pragma unroll
    for (int c = 0; c < NBC; c++){
        float a0 = 0.f, a1 = 0.f;
        #pragma unroll
        for (int j = 0; j < K0; j++){
            float w = skb[c*K0+j];
            float v = xw[K0-1-j];
            if (j & 1) a1 = fmaf(w, v, a1); else a0 = fmaf(w, v, a0);
        }
        g_drive[n*NBC+c] = a0 + a1;
    }
}

// ---------------- the sequential scan: 2 blocks (pathways) x 1 warp ----------------
__global__ void __launch_bounds__(32,1) scan_kernel(
    const float* __restrict__ P_sigoff, const float* __restrict__ P_lslope,
    const float* __restrict__ P_lp01,  const float* __restrict__ P_lp12,
    const float* __restrict__ P_lipc,  const float* __restrict__ P_lrrpc,
    const float* __restrict__ P_ipst,  const float* __restrict__ P_rrpst,
    const float* __restrict__ P_laclbc, const float* __restrict__ P_lbcacl,
    const float* __restrict__ P_acltr, const float* __restrict__ P_acltd,
    const float* __restrict__ P_aclsl, const float* __restrict__ P_aclof,
    const float* __restrict__ P_lacgbc, const float* __restrict__ P_lbcacg,
    const float* __restrict__ P_acgtr, const float* __restrict__ P_acgtd,
    const float* __restrict__ P_acgsl, const float* __restrict__ P_acgof,
    const float* __restrict__ P_laclacg, const float* __restrict__ P_bcnoff)
{
    const int path = blockIdx.x;
    const int l = threadIdx.x;
    __shared__ float ringA[NACL*53];
    __shared__ float ringG[NACG*53];
    __shared__ float dbuf[2][16*NBC];
    __shared__ __align__(16) float sm_tvA[12];
    __shared__ __align__(16) float sm_tvG[36];
    __shared__ __align__(16) float sm_rel[16];
    for (int i = l; i < NACL*53; i += 32) ringA[i] = 0.f;
    for (int i = l; i < NACG*53; i += 32) ringG[i] = 0.f;
    if (l < 12) sm_tvA[l] = 0.f;
    { int i = l; if (i < 36) sm_tvG[i] = 0.f; if (i+32 < 36) sm_tvG[i+32] = 0.f; }
    if (l < 16) sm_rel[l] = 0.f;

    // ---- BC role (lane < 14): exp-form final sigmoid, log2e+slope pre-folded ----
    float cP=0.f, mBC=0.f, c_p01=0.f, c_p12=0.f, c_ipcap=0.f, c_irrp=0.f;
    float ip=0.f, rrp=0.f;
    float wfbAE[12], wfbGE[36];
    #pragma unroll
    for (int j = 0; j < 12; j++) wfbAE[j] = 0.f;
    #pragma unroll
    for (int j = 0; j < 36; j++) wfbGE[j] = 0.f;
    if (l < NBC){
        float off   = P_sigoff[l] + (path ? P_bcnoff[l] : 0.f);
        float slope = expf(P_lslope[l]);
        mBC = -slope * 1.44269504f;          /* exp(-z) = 2^(mBC * total) */
        c_p01   = expf(P_lp01[l]);
        c_p12   = expf(P_lp12[l]);
        c_ipcap = expf(P_lipc[l]);
        float rc = expf(P_lrrpc[l]);
        c_irrp = 1.0f / rc;
        ip  = c_ipcap / (1.0f + expf(-P_ipst[l]));
        rrp = rc      / (1.0f + expf(-P_rrpst[l]));
        float sA = 0.f, sG = 0.f;
        #pragma unroll
        for (int j = 0; j < NACL; j++){
            float w = -expf(P_laclbc[l*NACL+j]);
            sA += w; wfbAE[j] = 0.5f*mBC*w;
        }
        if (path){
            #pragma unroll
            for (int j = 0; j < NACG; j++){
                float w = -expf(P_lacgbc[l*NACG+j]);
                sG += w; wfbGE[j] = 0.5f*mBC*w;
            }
        }
        cP = mBC*(0.5f*(sA+sG) - off);
    }

    // ---- ACL role (lane < 10): tanh-form, half-slope pre-folded into state ----
    float kA1=0.f,kA2=0.f,aR1=1.f,aR2=1.f,kA1c=0.f,kA2c=0.f,caA=0.f;
    float wyA[16];
    #pragma unroll
    for (int j = 0; j < 16; j++) wyA[j] = 0.f;
    if (l < NACL){
        float A,B,r1,r2,c1,c2;
        ac_coef(P_acltr[l], P_acltd[l], A,B,r1,r2,c1,c2);
        float ha = 0.5f*expf(P_aclsl[l]);
        kA1 = ha*A; kA2 = ha*B; aR1=r1; aR2=r2;
        kA1c = kA1*c1; kA2c = kA2*c2;
        caA = -ha*P_aclof[l];
        #pragma unroll
        for (int j = 0; j < NBC; j++) wyA[j] = expf(P_lbcacl[l*NBC+j]);
    }

    // ---- ACG roles (pathway 2 only): g = lane (0..31), h = lane+32 (lanes 0..2) ----
    float kG1=0.f,kG2=0.f,gR1=1.f,gR2=1.f,kG1c=0.f,kG2c=0.f,cgG=0.f;
    float kH1=0.f,kH2=0.f,hR1=1.f,hR2=1.f,kH1c=0.f,kH2c=0.f,cgH=0.f;
    float wGaE[12], wHaE[12], wyG[16], wyH[16];
    #pragma unroll
    for (int j = 0; j < 12; j++){ wGaE[j]=0.f; wHaE[j]=0.f; }
    #pragma unroll
    for (int j = 0; j < 16; j++){ wyG[j]=0.f; wyH[j]=0.f; }
    if (path){
        float A,B,r1,r2,c1,c2;
        ac_coef(P_acgtr[l], P_acgtd[l], A,B,r1,r2,c1,c2);
        float hg = 0.5f*expf(P_acgsl[l]);
        kG1 = hg*A; kG2 = hg*B; gR1=r1; gR2=r2;
        kG1c = kG1*c1; kG2c = kG2*c2;
        float sw = 0.f;
        #pragma unroll
        for (int j = 0; j < NACL; j++){
            float w = -expf(P_laclacg[l*NACL+j]);
            sw += w; wGaE[j] = hg*0.5f*w;
        }
        cgG = hg*(0.5f*sw - P_acgof[l]);
        #pragma unroll
        for (int j = 0; j < NBC; j++) wyG[j] = expf(P_lbcacg[l*NBC+j]);
        if (l < 3){
            int h = l + 32;
            ac_coef(P_acgtr[h], P_acgtd[h], A,B,r1,r2,c1,c2);
            float hh = 0.5f*expf(P_acgsl[h]);
            kH1 = hh*A; kH2 = hh*B; hR1=r1; hR2=r2;
            kH1c = kH1*c1; kH2c = kH2*c2;
            float swh = 0.f;
            #pragma unroll
            for (int j = 0; j < NACL; j++){
                float w = -expf(P_laclacg[h*NACL+j]);
                swh += w; wHaE[j] = hh*0.5f*w;
            }
            cgH = hh*(0.5f*swh - P_acgof[h]);
            #pragma unroll
            for (int j = 0; j < NBC; j++) wyH[j] = expf(P_lbcacg[h*NBC+j]);
        }
    }
    __syncwarp();

    float* relrow = g_rel + (path*NBC + ((l < NBC) ? l : 0))*RELSTRIDE;
    float A1=0.f,A2=0.f,G1=0.f,G2=0.f,H1=0.f,H2=0.f;
    int ri = 0;

    float fd0,fd1,fd2,fd3,fd4,fd5,fd6;
#define LOADCHUNK(k) do{ const float* _p = g_drive + (k)*224 + l; \
        fd0=_p[0]; fd1=_p[32]; fd2=_p[64]; fd3=_p[96]; fd4=_p[128]; fd5=_p[160]; fd6=_p[192]; }while(0)
#define STORECHUNK(bi) do{ float* _q = dbuf[bi] + l; \
        _q[0]=fd0; _q[32]=fd1; _q[64]=fd2; _q[96]=fd3; _q[128]=fd4; _q[160]=fd5; _q[192]=fd6; }while(0)

    LOADCHUNK(0); STORECHUNK(0); LOADCHUNK(1);
    __syncwarp();

    if (path == 0){
        // ---------- LNR pathway: ACL feedback only (shfl-based; not the limiter) ----------
        for (int c = 0; c < NCHUNK; c++){
            int cur = c & 1;
            STORECHUNK(cur^1);
            int nk = (c+2 < NCHUNK) ? (c+2) : (NCHUNK-1);
            LOADCHUNK(nk);
            __syncwarp();
            const float* db = dbuf[cur];
            int tbase = c*16;
            #pragma unroll 4
            for (int i = 0; i < 16; i++){
                float yoA = (l < NACL) ? ringA[l*53+ri] : 0.f;
                float xi  = (l < NBC) ? db[i*NBC + l] : 0.f;
                float t12 = c_p12*ip*(1.0f - rrp*c_irrp);
                float ip_n = ip + c_p01*(c_ipcap - ip) - t12;
                float rrp_m = rrp + t12;
                float bA1 = fmaf(-kA1c, yoA, aR1*A1);
                float bA2 = fmaf(-kA2c, yoA, aR2*A2);
                float tvA = ftanh((A1 - A2) + caA);
                float fb0 = fmaf(mBC, xi, cP), fb1 = 0.f;
                #pragma unroll
                for (int j = 0; j < NACL; j++){
                    float v = __shfl_sync(0xffffffffu, tvA, j);
                    if (j & 1) fb1 = fmaf(wfbAE[j], v, fb1);
                    else       fb0 = fmaf(wfbAE[j], v, fb0);
                }
                float e = fex2(fb0 + fb1);
                float relv = rrp * frcp(1.0f + e);
                ip = ip_n; rrp = rrp_m - relv;
                if (l < NBC) relrow[tbase+i] = relv;
                float y0 = 0.f, y1 = 0.f;
                #pragma unroll
                for (int j = 0; j < NBC; j++){
                    float v = __shfl_sync(0xffffffffu, relv, j);
                    if (j & 1) y1 = fmaf(wyA[j], v, y1);
                    else       y0 = fmaf(wyA[j], v, y0);
                }
                float yA = y0 + y1;
                if (l < NACL) ringA[l*53+ri] = yA;
                A1 = fmaf(kA1, yA, bA1);
                A2 = fmaf(kA2, yA, bA2);
                ri = (ri == KACN-1) ? 0 : ri+1;
            }
            __syncwarp();
        }
    } else {
        // ---------- BCN pathway: shuffle-free, smem-broadcast ----------
        const float4* SA = (const float4*)sm_tvA;
        const float4* SG = (const float4*)sm_tvG;
        const float4* SR = (const float4*)sm_rel;
        for (int c = 0; c < NCHUNK; c++){
            int cur = c & 1;
            STORECHUNK(cur^1);
            int nk = (c+2 < NCHUNK) ? (c+2) : (NCHUNK-1);
            LOADCHUNK(nk);
            __syncwarp();
            const float* db = dbuf[cur];
            int tbase = c*16;
            #pragma unroll 2
            for (int i = 0; i < 16; i++){
                /* ---- off-chain top work (all use OLD states) ---- */
                float yoA = (l < NACL) ? ringA[l*53+ri] : 0.f;
                float yoG = ringG[l*53+ri];
                float yoH = (l < 3) ? ringG[(l+32)*53+ri] : 0.f;
                float xi  = (l < NBC) ? db[i*NBC + l] : 0.f;
                float t12 = c_p12*ip*(1.0f - rrp*c_irrp);
                float ip_n = ip + c_p01*(c_ipcap - ip) - t12;
                float rrp_m = rrp + t12;
                float bA1 = fmaf(-kA1c, yoA, aR1*A1);
                float bA2 = fmaf(-kA2c, yoA, aR2*A2);
                float bG1 = fmaf(-kG1c, yoG, gR1*G1);
                float bG2 = fmaf(-kG2c, yoG, gR2*G2);
                float bH1 = fmaf(-kH1c, yoH, hR1*H1);
                float bH2 = fmaf(-kH2c, yoH, hR2*H2);
                float baseG = (G1 - G2) + cgG;
                float baseH = (H1 - H2) + cgH;
                /* ---- stage 1: ACL tanh, broadcast via smem ---- */
                float tvA = ftanh((A1 - A2) + caA);
                if (l < NACL) sm_tvA[l] = tvA;
                __syncwarp();
                float4 ta0 = SA[0], ta1 = SA[1], ta2 = SA[2];
                /* ---- stage 2: ACG pre-activations ---- */
                float pg0 = baseG, pg1 = 0.f, pg2 = 0.f;
                pg0 = fmaf(wGaE[0], ta0.x, pg0); pg1 = fmaf(wGaE[1], ta0.y, pg1); pg2 = fmaf(wGaE[2], ta0.z, pg2);
                pg0 = fmaf(wGaE[3], ta0.w, pg0); pg1 = fmaf(wGaE[4], ta1.x, pg1); pg2 = fmaf(wGaE[5], ta1.y, pg2);
                pg0 = fmaf(wGaE[6], ta1.z, pg0); pg1 = fmaf(wGaE[7], ta1.w, pg1); pg2 = fmaf(wGaE[8], ta2.x, pg2);
                pg0 = fmaf(wGaE[9], ta2.y, pg0);
                float ph0 = baseH, ph1 = 0.f, ph2 = 0.f;
                ph0 = fmaf(wHaE[0], ta0.x, ph0); ph1 = fmaf(wHaE[1], ta0.y, ph1); ph2 = fmaf(wHaE[2], ta0.z, ph2);
                ph0 = fmaf(wHaE[3], ta0.w, ph0); ph1 = fmaf(wHaE[4], ta1.x, ph1); ph2 = fmaf(wHaE[5], ta1.y, ph2);
                ph0 = fmaf(wHaE[6], ta1.z, ph0); ph1 = fmaf(wHaE[7], ta1.w, ph1); ph2 = fmaf(wHaE[8], ta2.x, ph2);
                ph0 = fmaf(wHaE[9], ta2.y, ph0);
                float tvG = ftanh(pg0 + (pg1 + pg2));
                float tvH = ftanh(ph0 + (ph1 + ph2));
                sm_tvG[l] = tvG;
                if (l < 3) sm_tvG[32+l] = tvH;
                __syncwarp();
                /* ---- stage 3: BC pre-activation (36 + 12 taps, vec4 broadcast) ---- */
                float4 q0=SG[0],q1=SG[1],q2=SG[2],q3=SG[3],q4=SG[4],q5=SG[5],q6=SG[6],q7=SG[7],q8=SG[8];
                float a0 = fmaf(mBC, xi, cP), a1=0.f,a2=0.f,a3=0.f,a4=0.f,a5=0.f,a6=0.f,a7=0.f;
                a0=fmaf(wfbGE[0],q0.x,a0); a1=fmaf(wfbGE[1],q0.y,a1); a2=fmaf(wfbGE[2],q0.z,a2); a3=fmaf(wfbGE[3],q0.w,a3);
                a4=fmaf(wfbGE[4],q1.x,a4); a5=fmaf(wfbGE[5],q1.y,a5); a6=fmaf(wfbGE[6],q1.z,a6); a7=fmaf(wfbGE[7],q1.w,a7);
                a0=fmaf(wfbGE[8],q2.x,a0); a1=fmaf(wfbGE[9],q2.y,a1); a2=fmaf(wfbGE[10],q2.z,a2); a3=fmaf(wfbGE[11],q2.w,a3);
                a4=fmaf(wfbGE[12],q3.x,a4); a5=fmaf(wfbGE[13],q3.y,a5); a6=fmaf(wfbGE[14],q3.z,a6); a7=fmaf(wfbGE[15],q3.w,a7);
                a0=fmaf(wfbGE[16],q4.x,a0); a1=fmaf(wfbGE[17],q4.y,a1); a2=fmaf(wfbGE[18],q4.z,a2); a3=fmaf(wfbGE[19],q4.w,a3);
                a4=fmaf(wfbGE[20],q5.x,a4); a5=fmaf(wfbGE[21],q5.y,a5); a6=fmaf(wfbGE[22],q5.z,a6); a7=fmaf(wfbGE[23],q5.w,a7);
                a0=fmaf(wfbGE[24],q6.x,a0); a1=fmaf(wfbGE[25],q6.y,a1); a2=fmaf(wfbGE[26],q6.z,a2); a3=fmaf(wfbGE[27],q6.w,a3);
                a4=fmaf(wfbGE[28],q7.x,a4); a5=fmaf(wfbGE[29],q7.y,a5); a6=fmaf(wfbGE[30],q7.z,a6); a7=fmaf(wfbGE[31],q7.w,a7);
                a0=fmaf(wfbGE[32],q8.x,a0); a1=fmaf(wfbGE[33],q8.y,a1); a2=fmaf(wfbGE[34],q8.z,a2); a3=fmaf(wfbGE[35],q8.w,a3);
                a4=fmaf(wfbAE[0],ta0.x,a4); a5=fmaf(wfbAE[1],ta0.y,a5); a6=fmaf(wfbAE[2],ta0.z,a6); a7=fmaf(wfbAE[3],ta0.w,a7);
                a0=fmaf(wfbAE[4],ta1.x,a0); a1=fmaf(wfbAE[5],ta1.y,a1); a2=fmaf(wfbAE[6],ta1.z,a2); a3=fmaf(wfbAE[7],ta1.w,a3);
                a4=fmaf(wfbAE[8],ta2.x,a4); a5=fmaf(wfbAE[9],ta2.y,a5);
                float s = ((a0+a1)+(a2+a3)) + ((a4+a5)+(a6+a7));
                float e = fex2(s);
                float relv = rrp * frcp(1.0f + e);
                ip = ip_n; rrp = rrp_m - relv;
                if (l < NBC){ relrow[tbase+i] = relv; sm_rel[l] = relv; }
                __syncwarp();
                /* ---- stage 4: release -> AC drive matvecs (vec4 broadcast) ---- */
                float4 r0 = SR[0], r1 = SR[1], r2 = SR[2], r3 = SR[3];
                float ya0,ya1,ya2,ya3, yg0,yg1,yg2,yg3, yh0,yh1,yh2,yh3;
                ya0 = wyA[0]*r0.x;  ya1 = wyA[1]*r0.y;  ya2 = wyA[2]*r0.z;  ya3 = wyA[3]*r0.w;
                yg0 = wyG[0]*r0.x;  yg1 = wyG[1]*r0.y;  yg2 = wyG[2]*r0.z;  yg3 = wyG[3]*r0.w;
                yh0 = wyH[0]*r0.x;  yh1 = wyH[1]*r0.y;  yh2 = wyH[2]*r0.z;  yh3 = wyH[3]*r0.w;
                ya0=fmaf(wyA[4],r1.x,ya0); ya1=fmaf(wyA[5],r1.y,ya1); ya2=fmaf(wyA[6],r1.z,ya2); ya3=fmaf(wyA[7],r1.w,ya3);
                yg0=fmaf(wyG[4],r1.x,yg0); yg1=fmaf(wyG[5],r1.y,yg1); yg2=fmaf(wyG[6],r1.z,yg2); yg3=fmaf(wyG[7],r1.w,yg3);
                yh0=fmaf(wyH[4],r1.x,yh0); yh1=fmaf(wyH[5],r1.y,yh1); yh2=fmaf(wyH[6],r1.z,yh2); yh3=fmaf(wyH[7],r1.w,yh3);
                ya0=fmaf(wyA[8],r2.x,ya0); ya1=fmaf(wyA[9],r2.y,ya1); ya2=fmaf(wyA[10],r2.z,ya2); ya3=fmaf(wyA[11],r2.w,ya3);
                yg0=fmaf(wyG[8],r2.x,yg0); yg1=fmaf(wyG[9],r2.y,yg1); yg2=fmaf(wyG[10],r2.z,yg2); yg3=fmaf(wyG[11],r2.w,yg3);
                yh0=fmaf(wyH[8],r2.x,yh0); yh1=fmaf(wyH[9],r2.y,yh1); yh2=fmaf(wyH[10],r2.z,yh2); yh3=fmaf(wyH[11],r2.w,yh3);
                ya0=fmaf(wyA[12],r3.x,ya0); ya1=fmaf(wyA[13],r3.y,ya1);
                yg0=fmaf(wyG[12],r3.x,yg0); yg1=fmaf(wyG[13],r3.y,yg1);
                yh0=fmaf(wyH[12],r3.x,yh0); yh1=fmaf(wyH[13],r3.y,yh1);
                float yA = (ya0+ya1)+(ya2+ya3);
                float yG = (yg0+yg1)+(yg2+yg3);
                float yH = (yh0+yh1)+(yh2+yh3);
                if (l < NACL) ringA[l*53+ri] = yA;
                ringG[l*53+ri] = yG;
                if (l < 3) ringG[(l+32)*53+ri] = yH;
                A1 = fmaf(kA1, yA, bA1);
                A2 = fmaf(kA2, yA, bA2);
                G1 = fmaf(kG1, yG, bG1);
                G2 = fmaf(kG2, yG, bG2);
                H1 = fmaf(kH1, yH, bH1);
                H2 = fmaf(kH2, yH, bH2);
                ri = (ri == KACN-1) ? 0 : ri+1;
            }
            __syncwarp();
        }
    }
#undef LOADCHUNK
#undef STORECHUNK
}

// ---------------- iGluSnFR readout: 32-tap FIR over rel ----------------
__global__ void out_kernel(float* __restrict__ out){
    __shared__ float skg[K1];
    int tid = threadIdx.x;
    if (tid < K1) skg[tid] = g_kglu[tid];
    __syncthreads();
    int oid = blockIdx.x*blockDim.x + tid;
    if (oid >= 2*NBC*TN) return;
    int n  = oid & (TN-1);
    int pc = oid >> 15;
    const float* r = g_rel + pc*RELSTRIDE + n;
    float a0 = 0.f, a1 = 0.f;
    #pragma unroll
    for (int j = 0; j < K1; j++){
        float v = r[K1-1-j];
        if (j & 1) a1 = fmaf(skg[j], v, a1);
        else       a0 = fmaf(skg[j], v, a0);
    }
    out[oid] = a0 + a1;
}

extern "C" void kernel_launch(void* const* d_in, const int* in_sizes, int n_in,
                              void* d_out, int out_size){
    (void)in_sizes; (void)n_in; (void)out_size;
    const float* x  = (const float*)d_in[0];
    const float* sb = (const float*)d_in[1];
    const float* ss = (const float*)d_in[2];

    setup_kernel<<<1, 64>>>((const float*)d_in[3]);
    xp_kernel<<<(XPLEN+255)/256, 256>>>(x, sb, ss);
    drive_kernel<<<(NSTEPS+127)/128, 128>>>();
    scan_kernel<<<2, 32>>>(
        (const float*)d_in[4],  (const float*)d_in[5],
        (const float*)d_in[6],  (const float*)d_in[7],
        (const float*)d_in[8],  (const float*)d_in[9],
        (const float*)d_in[10], (const float*)d_in[11],
        (const float*)d_in[12], (const float*)d_in[13],
        (const float*)d_in[14], (const float*)d_in[15],
        (const float*)d_in[16], (const float*)d_in[17],
        (const float*)d_in[18], (const float*)d_in[19],
        (const float*)d_in[20], (const float*)d_in[21],
        (const float*)d_in[22], (const float*)d_in[23],
        (const float*)d_in[24], (const float*)d_in[25]);
    out_kernel<<<(2*NBC*TN+255)/256, 256>>>((float*)d_out);
}